// round 1
// baseline (speedup 1.0000x reference)
#include <cuda_runtime.h>

#define T_LEN 4096
#define D_DIM 1024
#define NCTA  128
#define RCOLS (D_DIM / NCTA)   // 8 columns per CTA
#define REC_SMEM ((D_DIM + 3 * RCOLS * D_DIM) * sizeof(float))  // 100 KB

// ---------------- scratch (device globals: no allocation allowed) -----------
__device__ float g_Gr[T_LEN * D_DIM];
__device__ float g_Gz[T_LEN * D_DIM];
__device__ float g_Gn[T_LEN * D_DIM];
__device__ float g_ys[T_LEN * D_DIM];
__device__ unsigned int g_bar[T_LEN];

// ---------------- barrier counter reset (fresh each graph replay) ----------
__global__ void zero_bar_kernel() {
    int i = blockIdx.x * blockDim.x + threadIdx.x;
    if (i < T_LEN) g_bar[i] = 0u;
}

// ---------------- fp32 tiled GEMM: C = (relu?)(A) @ B + bias ----------------
// A: [M,K] row-major, B: [K,N] row-major, bias: [N]
template <bool RELU_A>
__global__ void __launch_bounds__(256) gemm_bias_kernel(
    const float* __restrict__ A, const float* __restrict__ B,
    const float* __restrict__ bias, float* __restrict__ C,
    int M, int N, int K)
{
    __shared__ float As[16][64];   // transposed: As[k][m]
    __shared__ float Bs[16][64];   // Bs[k][n]

    const int tid = threadIdx.x;
    const int tx = tid & 15, ty = tid >> 4;
    const int bm = blockIdx.y << 6, bn = blockIdx.x << 6;

    const int arow = tid >> 2, acol = (tid & 3) << 2;   // A tile: 64 rows x 16 k
    const int brow = tid >> 4, bcol = (tid & 15) << 2;  // B tile: 16 k x 64 cols

    const float* Ap = A + (size_t)(bm + arow) * K + acol;
    const float* Bp = B + (size_t)brow * N + bn + bcol;

    float acc[4][4];
#pragma unroll
    for (int i = 0; i < 4; i++)
#pragma unroll
        for (int j = 0; j < 4; j++) acc[i][j] = 0.f;

    for (int kb = 0; kb < K; kb += 16) {
        float4 a4 = *(const float4*)(Ap + kb);
        float4 b4 = *(const float4*)(Bp + (size_t)kb * N);
        if (RELU_A) {
            a4.x = fmaxf(a4.x, 0.f); a4.y = fmaxf(a4.y, 0.f);
            a4.z = fmaxf(a4.z, 0.f); a4.w = fmaxf(a4.w, 0.f);
        }
        As[acol + 0][arow] = a4.x;
        As[acol + 1][arow] = a4.y;
        As[acol + 2][arow] = a4.z;
        As[acol + 3][arow] = a4.w;
        *(float4*)&Bs[brow][bcol] = b4;
        __syncthreads();

#pragma unroll
        for (int kk = 0; kk < 16; kk++) {
            float4 av = *(const float4*)&As[kk][ty << 2];
            float4 bv = *(const float4*)&Bs[kk][tx << 2];
            float a_[4] = {av.x, av.y, av.z, av.w};
            float b_[4] = {bv.x, bv.y, bv.z, bv.w};
#pragma unroll
            for (int i = 0; i < 4; i++)
#pragma unroll
                for (int j = 0; j < 4; j++)
                    acc[i][j] = fmaf(a_[i], b_[j], acc[i][j]);
        }
        __syncthreads();
    }

    float4 bb = *(const float4*)&bias[bn + (tx << 2)];
#pragma unroll
    for (int i = 0; i < 4; i++) {
        float4 o = make_float4(acc[i][0] + bb.x, acc[i][1] + bb.y,
                               acc[i][2] + bb.z, acc[i][3] + bb.w);
        *(float4*)&C[(size_t)(bm + (ty << 2) + i) * N + bn + (tx << 2)] = o;
    }
}

// ---------------- persistent GRU recurrence (grid-wide sync per step) ------
// 128 CTAs x 256 threads. Each CTA owns 8 output columns; weight column
// slices (3 gates x 8 cols x 1024) resident in SMEM for all 4096 steps.
__global__ void __launch_bounds__(256, 1) gru_recurrence_kernel(
    const float* __restrict__ Whr, const float* __restrict__ Whz,
    const float* __restrict__ Whn, const float* __restrict__ bhn,
    const float* __restrict__ init_state)
{
    extern __shared__ float smem[];
    float* sh_h = smem;              // 1024 floats: h_{t-1}
    float* w_s  = smem + D_DIM;      // [3][RCOLS][1024], column-major slices

    const int tid  = threadIdx.x;
    const int cta  = blockIdx.x;
    const int col0 = cta * RCOLS;

    // one-time: stage this CTA's weight columns into SMEM
    for (int idx = tid; idx < RCOLS * D_DIM; idx += 256) {
        int c = idx >> 10, k = idx & (D_DIM - 1);
        int g = k * D_DIM + col0 + c;
        w_s[(0 * RCOLS + c) * D_DIM + k] = Whr[g];
        w_s[(1 * RCOLS + c) * D_DIM + k] = Whz[g];
        w_s[(2 * RCOLS + c) * D_DIM + k] = Whn[g];
    }
    __syncthreads();

    const int warp = tid >> 5, lane = tid & 31;
    const int c    = warp;                  // local column (8 warps = 8 cols)
    const int gcol = col0 + c;
    const float bhn_c = bhn[gcol];

    const float4* r4 = (const float4*)(w_s + (0 * RCOLS + c) * D_DIM);
    const float4* z4 = (const float4*)(w_s + (1 * RCOLS + c) * D_DIM);
    const float4* n4 = (const float4*)(w_s + (2 * RCOLS + c) * D_DIM);
    const float4* h4 = (const float4*)sh_h;

    volatile unsigned int* bar = g_bar;

    for (int t = 0; t < T_LEN; t++) {
        const float* hsrc = (t == 0) ? init_state : (g_ys + (size_t)(t - 1) * D_DIM);
        ((float4*)sh_h)[tid] = ((const float4*)hsrc)[tid];  // 256*4 = 1024
        __syncthreads();

        float ar = 0.f, az = 0.f, an = 0.f;
#pragma unroll
        for (int i = 0; i < 8; i++) {
            int idx = i * 32 + lane;        // lane-contiguous float4s: conflict-free
            float4 h = h4[idx];
            float4 r = r4[idx], z = z4[idx], n = n4[idx];
            ar += h.x * r.x + h.y * r.y + h.z * r.z + h.w * r.w;
            az += h.x * z.x + h.y * z.y + h.z * z.z + h.w * z.w;
            an += h.x * n.x + h.y * n.y + h.z * n.z + h.w * n.w;
        }
#pragma unroll
        for (int o = 16; o > 0; o >>= 1) {
            ar += __shfl_down_sync(0xFFFFFFFFu, ar, o);
            az += __shfl_down_sync(0xFFFFFFFFu, az, o);
            an += __shfl_down_sync(0xFFFFFFFFu, an, o);
        }

        if (lane == 0) {
            float gr = g_Gr[(size_t)t * D_DIM + gcol];
            float gz = g_Gz[(size_t)t * D_DIM + gcol];
            float gn = g_Gn[(size_t)t * D_DIM + gcol];
            float r = 1.f / (1.f + expf(-(gr + ar)));
            float z = 1.f / (1.f + expf(-(gz + az)));
            float n = tanhf(gn + r * (an + bhn_c));
            float hnew = (1.f - z) * n + z * sh_h[gcol];
            g_ys[(size_t)t * D_DIM + gcol] = hnew;
            __threadfence();                // make store visible GPU-wide
        }
        __syncthreads();                    // all 8 column stores done + fenced

        if (tid == 0) {
            atomicAdd((unsigned int*)&g_bar[t], 1u);   // arrive
            while (bar[t] < (unsigned int)NCTA) {}     // spin (volatile, L2)
            __threadfence();                           // acquire
        }
        __syncthreads();
    }
}

// ---------------- residual + layernorm (in-place on d_out) -----------------
__global__ void __launch_bounds__(256) layernorm_kernel(
    const float* __restrict__ xs, const float* __restrict__ ln_scale,
    const float* __restrict__ ln_bias, float* __restrict__ inout)
{
    __shared__ float red0[8], red1[8];
    const int t = blockIdx.x, tid = threadIdx.x;
    const float* xrow = xs + (size_t)t * D_DIM;
    float* yrow = inout + (size_t)t * D_DIM;

    float v[4];
    float s = 0.f, s2 = 0.f;
#pragma unroll
    for (int i = 0; i < 4; i++) {
        int idx = tid + i * 256;
        float y = xrow[idx] + yrow[idx];   // residual
        v[i] = y;
        s += y;
        s2 += y * y;
    }
#pragma unroll
    for (int o = 16; o > 0; o >>= 1) {
        s  += __shfl_down_sync(0xFFFFFFFFu, s,  o);
        s2 += __shfl_down_sync(0xFFFFFFFFu, s2, o);
    }
    const int warp = tid >> 5, lane = tid & 31;
    if (lane == 0) { red0[warp] = s; red1[warp] = s2; }
    __syncthreads();
    if (warp == 0) {
        float a = (lane < 8) ? red0[lane] : 0.f;
        float b = (lane < 8) ? red1[lane] : 0.f;
#pragma unroll
        for (int o = 4; o > 0; o >>= 1) {
            a += __shfl_down_sync(0xFFFFFFFFu, a, o);
            b += __shfl_down_sync(0xFFFFFFFFu, b, o);
        }
        if (lane == 0) { red0[0] = a; red1[0] = b; }
    }
    __syncthreads();

    const float mu   = red0[0] * (1.f / D_DIM);
    const float var  = red1[0] * (1.f / D_DIM) - mu * mu;
    const float rstd = rsqrtf(var + 1e-6f);
#pragma unroll
    for (int i = 0; i < 4; i++) {
        int idx = tid + i * 256;
        yrow[idx] = (v[i] - mu) * rstd * ln_scale[idx] + ln_bias[idx];
    }
}

// ---------------- launcher --------------------------------------------------
extern "C" void kernel_launch(void* const* d_in, const int* in_sizes, int n_in,
                              void* d_out, int out_size)
{
    const float* xs        = (const float*)d_in[0];
    const float* init_st   = (const float*)d_in[1];
    const float* Wir       = (const float*)d_in[2];
    const float* Wiz       = (const float*)d_in[3];
    const float* Win       = (const float*)d_in[4];
    const float* bir       = (const float*)d_in[5];
    const float* biz       = (const float*)d_in[6];
    const float* bin_      = (const float*)d_in[7];
    const float* Whr       = (const float*)d_in[8];
    const float* Whz       = (const float*)d_in[9];
    const float* Whn       = (const float*)d_in[10];
    const float* bhn       = (const float*)d_in[11];
    const float* Wl        = (const float*)d_in[12];
    const float* bl        = (const float*)d_in[13];
    const float* ln_scale  = (const float*)d_in[14];
    const float* ln_bias   = (const float*)d_in[15];
    float* out = (float*)d_out;

    void *pGr, *pGz, *pGn, *pYs;
    cudaGetSymbolAddress(&pGr, g_Gr);
    cudaGetSymbolAddress(&pGz, g_Gz);
    cudaGetSymbolAddress(&pGn, g_Gn);
    cudaGetSymbolAddress(&pYs, g_ys);

    dim3 gemm_grid(D_DIM / 64, T_LEN / 64);  // (16, 64)

    // 1) input-side gate pre-GEMMs (parallel over time)
    gemm_bias_kernel<false><<<gemm_grid, 256>>>(xs, Wir, bir, (float*)pGr,
                                                T_LEN, D_DIM, D_DIM);
    gemm_bias_kernel<false><<<gemm_grid, 256>>>(xs, Wiz, biz, (float*)pGz,
                                                T_LEN, D_DIM, D_DIM);
    gemm_bias_kernel<false><<<gemm_grid, 256>>>(xs, Win, bin_, (float*)pGn,
                                                T_LEN, D_DIM, D_DIM);

    // 2) reset grid-barrier counters (deterministic across graph replays)
    zero_bar_kernel<<<(T_LEN + 255) / 256, 256>>>();

    // 3) sequential recurrence: persistent grid, SMEM-resident weights
    cudaFuncSetAttribute(gru_recurrence_kernel,
                         cudaFuncAttributeMaxDynamicSharedMemorySize,
                         (int)REC_SMEM);
    gru_recurrence_kernel<<<NCTA, 256, REC_SMEM>>>(Whr, Whz, Whn, bhn, init_st);

    // 4) post dense: d_out = relu(ys) @ Wl + bl
    gemm_bias_kernel<true><<<gemm_grid, 256>>>((const float*)pYs, Wl, bl, out,
                                               T_LEN, D_DIM, D_DIM);

    // 5) residual + layernorm in-place on d_out
    layernorm_kernel<<<T_LEN, 256>>>(xs, ln_scale, ln_bias, out);
}

// round 2
// speedup vs baseline: 1.4571x; 1.4571x over previous
#include <cuda_runtime.h>

#define T_LEN 4096
#define D_DIM 1024
#define NCTA  128
#define CPC   8      // columns per CTA (= warps per CTA)

// ---------------- scratch (device globals: no allocation allowed) -----------
__device__ float  g_Gr[T_LEN * D_DIM];
__device__ float  g_Gz[T_LEN * D_DIM];
__device__ float  g_Gn[T_LEN * D_DIM];
__device__ float  g_ys[T_LEN * D_DIM];          // plain h history (for post GEMM)
__device__ float2 g_hs[T_LEN * D_DIM];          // {h, step_tag} fused word

// ---------------- PTX helpers ----------------------------------------------
__device__ __forceinline__ unsigned long long pack2(float lo, float hi) {
    unsigned long long r;
    asm("mov.b64 %0, {%1, %2};" : "=l"(r) : "f"(lo), "f"(hi));
    return r;
}
__device__ __forceinline__ void unpack2(unsigned long long v, float& lo, float& hi) {
    asm("mov.b64 {%0, %1}, %2;" : "=f"(lo), "=f"(hi) : "l"(v));
}
__device__ __forceinline__ void fma2(unsigned long long& d,
                                     unsigned long long a, unsigned long long b) {
    asm("fma.rn.f32x2 %0, %1, %2, %0;" : "+l"(d) : "l"(a), "l"(b));
}
__device__ __forceinline__ float4 ldvol_f4(const float4* p) {
    float4 v;
    asm volatile("ld.volatile.global.v4.f32 {%0,%1,%2,%3}, [%4];"
                 : "=f"(v.x), "=f"(v.y), "=f"(v.z), "=f"(v.w) : "l"(p));
    return v;
}
__device__ __forceinline__ void stvol_f2(float2* p, float a, float b) {
    asm volatile("st.volatile.global.v2.f32 [%0], {%1,%2};" :: "l"(p), "f"(a), "f"(b));
}

// ---------------- tag clear (fresh each graph replay) -----------------------
__global__ void clear_tags_kernel() {
    size_t i = (size_t)blockIdx.x * blockDim.x + threadIdx.x;   // float4 index
    ((float4*)g_hs)[i] = make_float4(0.f, 0.f, 0.f, 0.f);       // grid sized exactly
}

// ---------------- fp32 tiled GEMM: C = (relu?)(A) @ B + bias ----------------
template <bool RELU_A>
__global__ void __launch_bounds__(256) gemm_bias_kernel(
    const float* __restrict__ A, const float* __restrict__ B,
    const float* __restrict__ bias, float* __restrict__ C,
    int M, int N, int K)
{
    __shared__ float As[16][64];
    __shared__ float Bs[16][64];

    const int tid = threadIdx.x;
    const int tx = tid & 15, ty = tid >> 4;
    const int bm = blockIdx.y << 6, bn = blockIdx.x << 6;

    const int arow = tid >> 2, acol = (tid & 3) << 2;
    const int brow = tid >> 4, bcol = (tid & 15) << 2;

    const float* Ap = A + (size_t)(bm + arow) * K + acol;
    const float* Bp = B + (size_t)brow * N + bn + bcol;

    float acc[4][4];
#pragma unroll
    for (int i = 0; i < 4; i++)
#pragma unroll
        for (int j = 0; j < 4; j++) acc[i][j] = 0.f;

    for (int kb = 0; kb < K; kb += 16) {
        float4 a4 = *(const float4*)(Ap + kb);
        float4 b4 = *(const float4*)(Bp + (size_t)kb * N);
        if (RELU_A) {
            a4.x = fmaxf(a4.x, 0.f); a4.y = fmaxf(a4.y, 0.f);
            a4.z = fmaxf(a4.z, 0.f); a4.w = fmaxf(a4.w, 0.f);
        }
        As[acol + 0][arow] = a4.x;
        As[acol + 1][arow] = a4.y;
        As[acol + 2][arow] = a4.z;
        As[acol + 3][arow] = a4.w;
        *(float4*)&Bs[brow][bcol] = b4;
        __syncthreads();

#pragma unroll
        for (int kk = 0; kk < 16; kk++) {
            float4 av = *(const float4*)&As[kk][ty << 2];
            float4 bv = *(const float4*)&Bs[kk][tx << 2];
            float a_[4] = {av.x, av.y, av.z, av.w};
            float b_[4] = {bv.x, bv.y, bv.z, bv.w};
#pragma unroll
            for (int i = 0; i < 4; i++)
#pragma unroll
                for (int j = 0; j < 4; j++)
                    acc[i][j] = fmaf(a_[i], b_[j], acc[i][j]);
        }
        __syncthreads();
    }

    float4 bb = *(const float4*)&bias[bn + (tx << 2)];
#pragma unroll
    for (int i = 0; i < 4; i++) {
        float4 o = make_float4(acc[i][0] + bb.x, acc[i][1] + bb.y,
                               acc[i][2] + bb.z, acc[i][3] + bb.w);
        *(float4*)&C[(size_t)(bm + (ty << 2) + i) * N + bn + (tx << 2)] = o;
    }
}

// ---------------- persistent GRU recurrence: register weights, tag sync ----
// 128 CTAs x 256 threads. Warp w owns global column cta*8 + w.
// Thread lane holds weights for k in {2*(lane+32*i), 2*(lane+32*i)+1}, i=0..15
// (96 weight floats in registers as 48 packed f32x2 words).
__global__ void __launch_bounds__(256, 1) gru_recurrence_kernel(
    const float* __restrict__ Whr, const float* __restrict__ Whz,
    const float* __restrict__ Whn, const float* __restrict__ bhn,
    const float* __restrict__ init_state)
{
    __shared__ float sh_h[D_DIM];          // 4 KB: h_{t-1} (values only)

    const int tid  = threadIdx.x;
    const int warp = tid >> 5, lane = tid & 31;
    const int col  = blockIdx.x * CPC + warp;

    // ---- one-time: load this thread's weight slice into registers ----
    unsigned long long wr[16], wz[16], wn[16];
#pragma unroll
    for (int i = 0; i < 16; i++) {
        const int k0 = 2 * (lane + 32 * i);
        const size_t o0 = (size_t)k0 * D_DIM + col;
        const size_t o1 = (size_t)(k0 + 1) * D_DIM + col;
        wr[i] = pack2(Whr[o0], Whr[o1]);
        wz[i] = pack2(Whz[o0], Whz[o1]);
        wn[i] = pack2(Whn[o0], Whn[o1]);
    }
    const float bhn_c = bhn[col];

    float h_prev = init_state[col];                 // own column's h (lane 0 uses)
    float gr_c = g_Gr[col], gz_c = g_Gz[col], gn_c = g_Gn[col];  // step-0 gates

    const unsigned long long* sh_h2 = (const unsigned long long*)sh_h;

    for (int t = 0; t < T_LEN; t++) {
        // ---- prefetch next step's gate pre-activations (hidden latency) ----
        float grn = 0.f, gzn = 0.f, gnn = 0.f;
        if (lane == 0 && t + 1 < T_LEN) {
            const size_t o = (size_t)(t + 1) * D_DIM + col;
            grn = __ldg(&g_Gr[o]); gzn = __ldg(&g_Gz[o]); gnn = __ldg(&g_Gn[o]);
        }

        // ---- stage h_{t-1} into smem ----
        if (t == 0) {
            float4 v = ((const float4*)init_state)[tid];
            *(float4*)&sh_h[tid << 2] = v;
        } else {
            const float4* src = (const float4*)(g_hs + (size_t)(t - 1) * D_DIM);
            const float tagf = (float)t;            // producer wrote tag = (t-1)+1
            float4 a = ldvol_f4(src + tid);
            while (__float_as_uint(a.y) != __float_as_uint(tagf) ||
                   __float_as_uint(a.w) != __float_as_uint(tagf))
                a = ldvol_f4(src + tid);
            float4 b = ldvol_f4(src + tid + 256);
            while (__float_as_uint(b.y) != __float_as_uint(tagf) ||
                   __float_as_uint(b.w) != __float_as_uint(tagf))
                b = ldvol_f4(src + tid + 256);
            ((float2*)sh_h)[tid]       = make_float2(a.x, a.z);
            ((float2*)sh_h)[tid + 256] = make_float2(b.x, b.z);
        }
        __syncthreads();

        // ---- packed dot products: 3 gates, 2 accumulators each for ILP ----
        unsigned long long ar0 = 0, ar1 = 0, az0 = 0, az1 = 0, an0 = 0, an1 = 0;
#pragma unroll
        for (int i = 0; i < 16; i += 2) {
            unsigned long long h0 = sh_h2[lane + 32 * i];
            unsigned long long h1 = sh_h2[lane + 32 * (i + 1)];
            fma2(ar0, h0, wr[i]);  fma2(ar1, h1, wr[i + 1]);
            fma2(az0, h0, wz[i]);  fma2(az1, h1, wz[i + 1]);
            fma2(an0, h0, wn[i]);  fma2(an1, h1, wn[i + 1]);
        }
        float lo, hi, ar, az, an;
        unpack2(ar0, lo, hi); ar = lo + hi; unpack2(ar1, lo, hi); ar += lo + hi;
        unpack2(az0, lo, hi); az = lo + hi; unpack2(az1, lo, hi); az += lo + hi;
        unpack2(an0, lo, hi); an = lo + hi; unpack2(an1, lo, hi); an += lo + hi;
#pragma unroll
        for (int o = 16; o > 0; o >>= 1) {
            ar += __shfl_xor_sync(0xFFFFFFFFu, ar, o);
            az += __shfl_xor_sync(0xFFFFFFFFu, az, o);
            an += __shfl_xor_sync(0xFFFFFFFFu, an, o);
        }

        // ---- gate math + publish (lane 0 of each warp) ----
        if (lane == 0) {
            float r = 1.f / (1.f + __expf(-(gr_c + ar)));
            float z = 1.f / (1.f + __expf(-(gz_c + az)));
            float nx = gn_c + r * (an + bhn_c);
            float n = 1.f - 2.f / (1.f + __expf(2.f * nx));   // tanh(nx)
            float hnew = (1.f - z) * n + z * h_prev;
            stvol_f2(g_hs + (size_t)t * D_DIM + col, hnew, (float)(t + 1));
            g_ys[(size_t)t * D_DIM + col] = hnew;
            h_prev = hnew;
            gr_c = grn; gz_c = gzn; gn_c = gnn;
        }
        __syncthreads();   // protect sh_h before next step's staging overwrites
    }
}

// ---------------- residual + layernorm (in-place on d_out) -----------------
__global__ void __launch_bounds__(256) layernorm_kernel(
    const float* __restrict__ xs, const float* __restrict__ ln_scale,
    const float* __restrict__ ln_bias, float* __restrict__ inout)
{
    __shared__ float red0[8], red1[8];
    const int t = blockIdx.x, tid = threadIdx.x;
    const float* xrow = xs + (size_t)t * D_DIM;
    float* yrow = inout + (size_t)t * D_DIM;

    float v[4];
    float s = 0.f, s2 = 0.f;
#pragma unroll
    for (int i = 0; i < 4; i++) {
        int idx = tid + i * 256;
        float y = xrow[idx] + yrow[idx];
        v[i] = y; s += y; s2 += y * y;
    }
#pragma unroll
    for (int o = 16; o > 0; o >>= 1) {
        s  += __shfl_down_sync(0xFFFFFFFFu, s,  o);
        s2 += __shfl_down_sync(0xFFFFFFFFu, s2, o);
    }
    const int warp = tid >> 5, lane = tid & 31;
    if (lane == 0) { red0[warp] = s; red1[warp] = s2; }
    __syncthreads();
    if (warp == 0) {
        float a = (lane < 8) ? red0[lane] : 0.f;
        float b = (lane < 8) ? red1[lane] : 0.f;
#pragma unroll
        for (int o = 4; o > 0; o >>= 1) {
            a += __shfl_down_sync(0xFFFFFFFFu, a, o);
            b += __shfl_down_sync(0xFFFFFFFFu, b, o);
        }
        if (lane == 0) { red0[0] = a; red1[0] = b; }
    }
    __syncthreads();

    const float mu   = red0[0] * (1.f / D_DIM);
    const float var  = red1[0] * (1.f / D_DIM) - mu * mu;
    const float rstd = rsqrtf(var + 1e-6f);
#pragma unroll
    for (int i = 0; i < 4; i++) {
        int idx = tid + i * 256;
        yrow[idx] = (v[i] - mu) * rstd * ln_scale[idx] + ln_bias[idx];
    }
}

// ---------------- launcher --------------------------------------------------
extern "C" void kernel_launch(void* const* d_in, const int* in_sizes, int n_in,
                              void* d_out, int out_size)
{
    const float* xs        = (const float*)d_in[0];
    const float* init_st   = (const float*)d_in[1];
    const float* Wir       = (const float*)d_in[2];
    const float* Wiz       = (const float*)d_in[3];
    const float* Win       = (const float*)d_in[4];
    const float* bir       = (const float*)d_in[5];
    const float* biz       = (const float*)d_in[6];
    const float* bin_      = (const float*)d_in[7];
    const float* Whr       = (const float*)d_in[8];
    const float* Whz       = (const float*)d_in[9];
    const float* Whn       = (const float*)d_in[10];
    const float* bhn       = (const float*)d_in[11];
    const float* Wl        = (const float*)d_in[12];
    const float* bl        = (const float*)d_in[13];
    const float* ln_scale  = (const float*)d_in[14];
    const float* ln_bias   = (const float*)d_in[15];
    float* out = (float*)d_out;

    void *pGr, *pGz, *pGn, *pYs;
    cudaGetSymbolAddress(&pGr, g_Gr);
    cudaGetSymbolAddress(&pGz, g_Gz);
    cudaGetSymbolAddress(&pGn, g_Gn);
    cudaGetSymbolAddress(&pYs, g_ys);

    dim3 gemm_grid(D_DIM / 64, T_LEN / 64);

    // 1) clear h tags (graph-replay determinism); 2M float4 words
    clear_tags_kernel<<<(T_LEN * D_DIM * 2 / 4) / 256, 256>>>();

    // 2) input-side gate pre-GEMMs (parallel over time)
    gemm_bias_kernel<false><<<gemm_grid, 256>>>(xs, Wir, bir, (float*)pGr,
                                                T_LEN, D_DIM, D_DIM);
    gemm_bias_kernel<false><<<gemm_grid, 256>>>(xs, Wiz, biz, (float*)pGz,
                                                T_LEN, D_DIM, D_DIM);
    gemm_bias_kernel<false><<<gemm_grid, 256>>>(xs, Win, bin_, (float*)pGn,
                                                T_LEN, D_DIM, D_DIM);

    // 3) sequential recurrence: persistent grid, register-resident weights
    gru_recurrence_kernel<<<NCTA, 256>>>(Whr, Whz, Whn, bhn, init_st);

    // 4) post dense: d_out = relu(ys) @ Wl + bl
    gemm_bias_kernel<true><<<gemm_grid, 256>>>((const float*)pYs, Wl, bl, out,
                                               T_LEN, D_DIM, D_DIM);

    // 5) residual + layernorm in-place on d_out
    layernorm_kernel<<<T_LEN, 256>>>(xs, ln_scale, ln_bias, out);
}